// round 8
// baseline (speedup 1.0000x reference)
#include <cuda_runtime.h>
#include <cuda_fp16.h>

#define NN 100000
#define EE 1600000
#define ET (EE + NN)
#define GG 2048
#define NBLK ((NN + 1023) / 1024)
#define WPB 8

typedef unsigned long long u64;

// ---------------- scratch (device globals; no allocation) ----------------
__device__ __align__(16) __half g_Hh[(size_t)NN * 64];  // fp16 transformed features
__device__ __align__(16) float  g_A[(size_t)NN * 64];   // aggregated output
__device__ __align__(16) float  g_als[NN * 4];
__device__ __align__(16) float  g_ald[NN * 4];
__device__ int g_deg[NN];       // zero-initialized at load; re-zeroed by pool_kernel
__device__ int g_scan[NN];
__device__ int g_rowptr[NN];
__device__ int g_cursor[NN];
__device__ int g_bsum[NBLK];
__device__ int g_csrc[ET];

__device__ __forceinline__ float lrelu(float x) { return x > 0.f ? x : 0.2f * x; }

// f32x2 packed FMA (Blackwell FFMA2)
__device__ __forceinline__ void fma2(u64& d, u64 a, u64 b) {
    asm("fma.rn.f32x2 %0,%1,%2,%0;" : "+l"(d) : "l"(a), "l"(b));
}
__device__ __forceinline__ float2 unpack2(u64 v) {
    float x, y; asm("mov.b64 {%0,%1},%2;" : "=f"(x), "=f"(y) : "l"(v));
    return make_float2(x, y);
}

// ---------------- CSR build ----------------
// g_deg must be zero at entry: zero-init at load, re-zeroed by pool_kernel.
__global__ void hist_kernel(const int* __restrict__ ei) {
    int i = blockIdx.x * blockDim.x + threadIdx.x;
    if (i >= ET) return;
    int dst = (i < EE) ? ei[EE + i] : (i - EE);
    atomicAdd(&g_deg[dst], 1);
}

__global__ void scan1_kernel() {
    __shared__ int buf[1024];
    int t = threadIdx.x;
    int i = blockIdx.x * 1024 + t;
    int v = (i < NN) ? g_deg[i] : 0;
    buf[t] = v;
    __syncthreads();
    for (int off = 1; off < 1024; off <<= 1) {
        int add = (t >= off) ? buf[t - off] : 0;
        __syncthreads();
        buf[t] += add;
        __syncthreads();
    }
    if (i < NN) g_scan[i] = buf[t];
    if (t == 1023) g_bsum[blockIdx.x] = buf[1023];
}

// fused scan2+scan3: each block re-scans the 98 block sums locally
__global__ void scan3_kernel() {
    __shared__ int sb[128];
    __shared__ int ex[128];
    int t = threadIdx.x;
    int v0 = 0;
    if (t < 128) {
        v0 = (t < NBLK) ? g_bsum[t] : 0;
        sb[t] = v0;
    }
    __syncthreads();
    for (int off = 1; off < 128; off <<= 1) {
        int add = (t < 128 && t >= off) ? sb[t - off] : 0;
        __syncthreads();
        if (t < 128) sb[t] += add;
        __syncthreads();
    }
    if (t < 128) ex[t] = sb[t] - v0;  // exclusive
    __syncthreads();

    int i = blockIdx.x * blockDim.x + t;
    if (i >= NN) return;
    int rp = g_scan[i] - g_deg[i] + ex[i >> 10];
    g_rowptr[i] = rp;
    g_cursor[i] = rp;
}

__global__ void scatter_kernel(const int* __restrict__ ei) {
    int i = blockIdx.x * blockDim.x + threadIdx.x;
    if (i >= ET) return;
    int src, dst;
    if (i < EE) { src = ei[i]; dst = ei[EE + i]; }
    else        { src = i - EE; dst = i - EE; }
    int pos = atomicAdd(&g_cursor[dst], 1);
    g_csrc[pos] = src;
}

// ---------------- fused GEMM + attention logits (register-tiled v2) -------
// Block: 256 threads, tile 128 nodes x 64 channels, K in chunks of 32.
// Thread (c8 = tid&7, n4 = tid>>3) computes nodes [4*n4,4*n4+4) x ch [8*c8,8*c8+8).
// x tile stored DUPLICATED in smem ((v,v) pairs) -> inner loop is pure
// 4x LDS.128 + 16x FFMA2 per k, no packing MOVs.
#define XSTRIDE 264   // 128 nodes * 2 + 8 pad floats
template <int FIN, bool FROM_A>
__global__ void __launch_bounds__(256)
gemm_attn_kernel(const float* __restrict__ xin_ext,
                 const float* __restrict__ W,
                 const float* __restrict__ a_src,
                 const float* __restrict__ a_dst,
                 const float* __restrict__ pbias) {
    constexpr int NCH = FIN / 32;                    // K chunks
    __shared__ __align__(16) float Ws[32 * 64];      // W chunk [k][64]
    __shared__ __align__(16) float Xt[32 * XSTRIDE]; // x chunk transposed+duplicated
    __shared__ float Aat[128];                       // [0:64) a_src, [64:128) a_dst
    __shared__ float Pb[FIN <= 64 ? 64 : FIN];

    int tid = threadIdx.x;
    int nbase = blockIdx.x * 128;
    int c8 = tid & 7;
    int n4 = tid >> 3;

    if (tid < 64)       Aat[tid] = a_src[tid];
    else if (tid < 128) Aat[tid] = a_dst[tid - 64];
    if (FROM_A) {
        for (int i = tid; i < FIN; i += 256) Pb[i] = pbias[i];
    }

    const float* xin = FROM_A ? (const float*)g_A : xin_ext;

    u64 acc[16];
#pragma unroll
    for (int j = 0; j < 16; j++) acc[j] = 0ull;

    for (int ch = 0; ch < NCH; ch++) {
        __syncthreads();
        // load W chunk (32 rows x 64 ch)
        for (int i = tid; i < 32 * 64; i += 256) Ws[i] = W[ch * 32 * 64 + i];
        // stage x chunk transposed + duplicated: idx -> (node, k4), 8 float4/node
        for (int idx = tid; idx < 128 * 8; idx += 256) {
            int node = idx & 127;
            int k4 = idx >> 7;          // 0..7, covers k = 4*k4..4*k4+3
            int gn = nbase + node;
            float4 v = make_float4(0.f, 0.f, 0.f, 0.f);
            if (gn < NN)
                v = reinterpret_cast<const float4*>(xin + (size_t)gn * FIN)[ch * 8 + k4];
            if (FROM_A) {
                v.x = fmaxf(v.x + Pb[ch * 32 + 4 * k4 + 0], 0.f);
                v.y = fmaxf(v.y + Pb[ch * 32 + 4 * k4 + 1], 0.f);
                v.z = fmaxf(v.z + Pb[ch * 32 + 4 * k4 + 2], 0.f);
                v.w = fmaxf(v.w + Pb[ch * 32 + 4 * k4 + 3], 0.f);
            }
            float2* xrow0 = reinterpret_cast<float2*>(&Xt[(4 * k4 + 0) * XSTRIDE]);
            float2* xrow1 = reinterpret_cast<float2*>(&Xt[(4 * k4 + 1) * XSTRIDE]);
            float2* xrow2 = reinterpret_cast<float2*>(&Xt[(4 * k4 + 2) * XSTRIDE]);
            float2* xrow3 = reinterpret_cast<float2*>(&Xt[(4 * k4 + 3) * XSTRIDE]);
            xrow0[node] = make_float2(v.x, v.x);
            xrow1[node] = make_float2(v.y, v.y);
            xrow2[node] = make_float2(v.z, v.z);
            xrow3[node] = make_float2(v.w, v.w);
        }
        __syncthreads();

#pragma unroll 4
        for (int k = 0; k < 32; k++) {
            const double2* wp = reinterpret_cast<const double2*>(&Ws[k * 64 + c8 * 8]);
            double2 wa = wp[0], wb = wp[1];
            const double2* xp =
                reinterpret_cast<const double2*>(&Xt[k * XSTRIDE + n4 * 8]);
            double2 xa = xp[0], xb = xp[1];
            u64 w0 = (u64)__double_as_longlong(wa.x);
            u64 w1 = (u64)__double_as_longlong(wa.y);
            u64 w2 = (u64)__double_as_longlong(wb.x);
            u64 w3 = (u64)__double_as_longlong(wb.y);
            u64 x0 = (u64)__double_as_longlong(xa.x);
            u64 x1 = (u64)__double_as_longlong(xa.y);
            u64 x2 = (u64)__double_as_longlong(xb.x);
            u64 x3 = (u64)__double_as_longlong(xb.y);
            fma2(acc[ 0], x0, w0); fma2(acc[ 1], x0, w1);
            fma2(acc[ 2], x0, w2); fma2(acc[ 3], x0, w3);
            fma2(acc[ 4], x1, w0); fma2(acc[ 5], x1, w1);
            fma2(acc[ 6], x1, w2); fma2(acc[ 7], x1, w3);
            fma2(acc[ 8], x2, w0); fma2(acc[ 9], x2, w1);
            fma2(acc[10], x2, w2); fma2(acc[11], x2, w3);
            fma2(acc[12], x3, w0); fma2(acc[13], x3, w1);
            fma2(acc[14], x3, w2); fma2(acc[15], x3, w3);
        }
    }

    // ---- epilogue ----
    // thread owns channels [8*c8, 8*c8+8) = half of head (c8>>1); pair via xor 1.
    int head = c8 >> 1;
    float As[8], Ad[8];
#pragma unroll
    for (int j = 0; j < 8; j++) {
        As[j] = Aat[c8 * 8 + j];
        Ad[j] = Aat[64 + c8 * 8 + j];
    }

#pragma unroll
    for (int nn = 0; nn < 4; nn++) {
        float2 f0 = unpack2(acc[nn * 4 + 0]);
        float2 f1 = unpack2(acc[nn * 4 + 1]);
        float2 f2 = unpack2(acc[nn * 4 + 2]);
        float2 f3 = unpack2(acc[nn * 4 + 3]);
        int gn = nbase + n4 * 4 + nn;

        if (gn < NN) {
            __half2 h0 = __floats2half2_rn(f0.x, f0.y);
            __half2 h1 = __floats2half2_rn(f1.x, f1.y);
            __half2 h2 = __floats2half2_rn(f2.x, f2.y);
            __half2 h3 = __floats2half2_rn(f3.x, f3.y);
            uint4 pk;
            pk.x = *reinterpret_cast<unsigned*>(&h0);
            pk.y = *reinterpret_cast<unsigned*>(&h1);
            pk.z = *reinterpret_cast<unsigned*>(&h2);
            pk.w = *reinterpret_cast<unsigned*>(&h3);
            *reinterpret_cast<uint4*>(g_Hh + (size_t)gn * 64 + c8 * 8) = pk;
        }

        float ss = f0.x * As[0] + f0.y * As[1] + f1.x * As[2] + f1.y * As[3]
                 + f2.x * As[4] + f2.y * As[5] + f3.x * As[6] + f3.y * As[7];
        float dd = f0.x * Ad[0] + f0.y * Ad[1] + f1.x * Ad[2] + f1.y * Ad[3]
                 + f2.x * Ad[4] + f2.y * Ad[5] + f3.x * Ad[6] + f3.y * Ad[7];
        ss += __shfl_xor_sync(0xFFFFFFFFu, ss, 1);
        dd += __shfl_xor_sync(0xFFFFFFFFu, dd, 1);
        if ((c8 & 1) == 0 && gn < NN) {
            g_als[gn * 4 + head] = ss;
            g_ald[gn * 4 + head] = dd;
        }
    }
}

// ---------------- fused softmax + aggregation (gather, warp per dst node) ----
__global__ void __launch_bounds__(256) gat_aggregate_kernel() {
    __shared__ int    s_s[WPB][32];
    __shared__ float4 s_w[WPB][32];

    int w = threadIdx.x >> 5;
    int lane = threadIdx.x & 31;
    int n = blockIdx.x * WPB + w;
    if (n >= NN) return;

    int beg = g_rowptr[n];
    int deg = g_deg[n];
    float4 ad = *reinterpret_cast<const float4*>(g_ald + n * 4);

    int head = lane >> 3;          // lane owns channels (2*lane, 2*lane+1)
    float accx = 0.f, accy = 0.f;
    float4 sw;

    const __half2* Hp = reinterpret_cast<const __half2*>(g_Hh);

    if (deg <= 32) {
        // ---- fast path: single gather of als, one chunk ----
        int s_reg = 0;
        float4 a = make_float4(-1e30f, -1e30f, -1e30f, -1e30f);
        bool act = lane < deg;
        if (act) {
            s_reg = g_csrc[beg + lane];
            a = *reinterpret_cast<const float4*>(g_als + s_reg * 4);
        }
        float4 mx = a;
#pragma unroll
        for (int off = 16; off; off >>= 1) {
            mx.x = fmaxf(mx.x, __shfl_xor_sync(0xFFFFFFFFu, mx.x, off));
            mx.y = fmaxf(mx.y, __shfl_xor_sync(0xFFFFFFFFu, mx.y, off));
            mx.z = fmaxf(mx.z, __shfl_xor_sync(0xFFFFFFFFu, mx.z, off));
            mx.w = fmaxf(mx.w, __shfl_xor_sync(0xFFFFFFFFu, mx.w, off));
        }
        float m0 = lrelu(mx.x + ad.x), m1 = lrelu(mx.y + ad.y);
        float m2 = lrelu(mx.z + ad.z), m3 = lrelu(mx.w + ad.w);

        float4 wv = make_float4(0.f, 0.f, 0.f, 0.f);
        if (act) {
            wv.x = __expf(lrelu(a.x + ad.x) - m0);
            wv.y = __expf(lrelu(a.y + ad.y) - m1);
            wv.z = __expf(lrelu(a.z + ad.z) - m2);
            wv.w = __expf(lrelu(a.w + ad.w) - m3);
            s_s[w][lane] = s_reg;
            s_w[w][lane] = wv;
        }
        sw = wv;
        __syncwarp();

        const float* wp = reinterpret_cast<const float*>(&s_w[w][0]);
#pragma unroll 8
        for (int j = 0; j < deg; j++) {
            int s0 = s_s[w][j];
            float w0 = wp[j * 4 + head];
            float2 f = __half22float2(Hp[(size_t)s0 * 32 + lane]);
            accx = fmaf(w0, f.x, accx);
            accy = fmaf(w0, f.y, accy);
        }
    } else {
        // ---- general path (rare): two-pass chunked ----
        float4 mx = make_float4(-1e30f, -1e30f, -1e30f, -1e30f);
        for (int i = lane; i < deg; i += 32) {
            int s = g_csrc[beg + i];
            float4 a = *reinterpret_cast<const float4*>(g_als + s * 4);
            mx.x = fmaxf(mx.x, a.x); mx.y = fmaxf(mx.y, a.y);
            mx.z = fmaxf(mx.z, a.z); mx.w = fmaxf(mx.w, a.w);
        }
#pragma unroll
        for (int off = 16; off; off >>= 1) {
            mx.x = fmaxf(mx.x, __shfl_xor_sync(0xFFFFFFFFu, mx.x, off));
            mx.y = fmaxf(mx.y, __shfl_xor_sync(0xFFFFFFFFu, mx.y, off));
            mx.z = fmaxf(mx.z, __shfl_xor_sync(0xFFFFFFFFu, mx.z, off));
            mx.w = fmaxf(mx.w, __shfl_xor_sync(0xFFFFFFFFu, mx.w, off));
        }
        float m0 = lrelu(mx.x + ad.x), m1 = lrelu(mx.y + ad.y);
        float m2 = lrelu(mx.z + ad.z), m3 = lrelu(mx.w + ad.w);

        sw = make_float4(0.f, 0.f, 0.f, 0.f);
        for (int base = 0; base < deg; base += 32) {
            int i = base + lane;
            if (i < deg) {
                int s = g_csrc[beg + i];
                float4 a = *reinterpret_cast<const float4*>(g_als + s * 4);
                float4 wv;
                wv.x = __expf(lrelu(a.x + ad.x) - m0);
                wv.y = __expf(lrelu(a.y + ad.y) - m1);
                wv.z = __expf(lrelu(a.z + ad.z) - m2);
                wv.w = __expf(lrelu(a.w + ad.w) - m3);
                sw.x += wv.x; sw.y += wv.y; sw.z += wv.z; sw.w += wv.w;
                s_s[w][lane] = s;
                s_w[w][lane] = wv;
            }
            __syncwarp();
            int cnt = min(32, deg - base);
            const float* wp = reinterpret_cast<const float*>(&s_w[w][0]);
#pragma unroll 8
            for (int j = 0; j < cnt; j++) {
                int s0 = s_s[w][j];
                float w0 = wp[j * 4 + head];
                float2 f = __half22float2(Hp[(size_t)s0 * 32 + lane]);
                accx = fmaf(w0, f.x, accx);
                accy = fmaf(w0, f.y, accy);
            }
            __syncwarp();
        }
    }

    // warp-reduce the exp sums
#pragma unroll
    for (int off = 16; off; off >>= 1) {
        sw.x += __shfl_xor_sync(0xFFFFFFFFu, sw.x, off);
        sw.y += __shfl_xor_sync(0xFFFFFFFFu, sw.y, off);
        sw.z += __shfl_xor_sync(0xFFFFFFFFu, sw.z, off);
        sw.w += __shfl_xor_sync(0xFFFFFFFFu, sw.w, off);
    }
    float sh = (head == 0) ? sw.x : (head == 1) ? sw.y : (head == 2) ? sw.z : sw.w;
    float inv = 1.f / (sh + 1e-16f);
    *reinterpret_cast<float2*>(g_A + (size_t)n * 64 + 2 * lane) =
        make_float2(accx * inv, accy * inv);
}

// ---------------- output init + pooling + head ----------------
__global__ void init_out_kernel(float* out, const float* __restrict__ hb) {
    int g = blockIdx.x * blockDim.x + threadIdx.x;
    if (g < GG) out[g] = hb[0];
}

__global__ void pool_kernel(const float* __restrict__ b2,
                            const float* __restrict__ hw,
                            const int* __restrict__ batch,
                            float* out) {
    __shared__ float sb[64], sw[64];
    int tid = threadIdx.x;
    if (tid < 64) { sb[tid] = b2[tid]; sw[tid] = hw[tid]; }
    __syncthreads();

    long long t = (long long)blockIdx.x * blockDim.x + tid;
    int n = (int)(t >> 5);
    int lane = (int)(t & 31);
    if (n >= NN) return;

    const float* ar = g_A + (size_t)n * 64;
    float sm = fmaxf(ar[lane] + sb[lane], 0.f) * sw[lane]
             + fmaxf(ar[lane + 32] + sb[lane + 32], 0.f) * sw[lane + 32];
#pragma unroll
    for (int off = 16; off > 0; off >>= 1)
        sm += __shfl_down_sync(0xFFFFFFFFu, sm, off);
    if (lane == 0) {
        atomicAdd(&out[batch[n]], sm);
        g_deg[n] = 0;   // restore CSR-build invariant for the next replay
    }
}

// ---------------- launch ----------------
extern "C" void kernel_launch(void* const* d_in, const int* in_sizes, int n_in,
                              void* d_out, int out_size) {
    const float* x     = (const float*)d_in[0];
    const int*   ei    = (const int*)d_in[1];
    const int*   batch = (const int*)d_in[2];
    const float* W0  = (const float*)d_in[3];
    const float* as0 = (const float*)d_in[4];
    const float* ad0 = (const float*)d_in[5];
    const float* b0  = (const float*)d_in[6];
    const float* W1  = (const float*)d_in[7];
    const float* as1 = (const float*)d_in[8];
    const float* ad1 = (const float*)d_in[9];
    const float* b1  = (const float*)d_in[10];
    const float* W2  = (const float*)d_in[11];
    const float* as2 = (const float*)d_in[12];
    const float* ad2 = (const float*)d_in[13];
    const float* b2  = (const float*)d_in[14];
    const float* hw  = (const float*)d_in[15];
    const float* hb  = (const float*)d_in[16];
    float* out = (float*)d_out;

    const int EB = (ET + 255) / 256;
    const int NB = (NN + 255) / 256;
    const int GB = (NN + 127) / 128;  // 128 nodes per 256-thread block
    const int AB = (NN + WPB - 1) / WPB;
    const int PB = (int)(((long long)NN * 32 + 255) / 256);

    // CSR build; gemm0 at launch index 3 so ncu captures it
    hist_kernel<<<EB, 256>>>(ei);                                        // 0
    scan1_kernel<<<NBLK, 1024>>>();                                      // 1
    scan3_kernel<<<NB, 256>>>();                                         // 2
    gemm_attn_kernel<128, false><<<GB, 256>>>(x, W0, as0, ad0, nullptr); // 3
    scatter_kernel<<<EB, 256>>>(ei);                                     // 4

    // layer 0 aggregate
    gat_aggregate_kernel<<<AB, 256>>>();

    // layer 1 (input = g_A with bias b0 + relu)
    gemm_attn_kernel<64, true><<<GB, 256>>>(nullptr, W1, as1, ad1, b0);
    gat_aggregate_kernel<<<AB, 256>>>();

    // layer 2 (input = g_A with bias b1 + relu)
    gemm_attn_kernel<64, true><<<GB, 256>>>(nullptr, W2, as2, ad2, b1);
    gat_aggregate_kernel<<<AB, 256>>>();

    // pooling + head (bias b2 + relu fused; also re-zeros g_deg)
    init_out_kernel<<<(GG + 255) / 256, 256>>>(out, hb);
    pool_kernel<<<PB, 256>>>(b2, hw, batch, out);
}

// round 10
// speedup vs baseline: 1.1180x; 1.1180x over previous
#include <cuda_runtime.h>
#include <cuda_fp16.h>

#define NN 100000
#define EE 1600000
#define ET (EE + NN)
#define GG 2048
#define NBLK ((NN + 1023) / 1024)
#define WPB 8

typedef unsigned long long u64;

// ---------------- scratch (device globals; no allocation) ----------------
__device__ __align__(16) __half g_Hh[(size_t)NN * 64];  // fp16 transformed features
__device__ __align__(16) float  g_A[(size_t)NN * 64];   // aggregated output
__device__ __align__(16) float  g_als[NN * 4];
__device__ __align__(16) float  g_ald[NN * 4];
__device__ int g_deg[NN];       // zero-initialized at load; re-zeroed by pool_kernel
__device__ int g_scan[NN];
__device__ int g_rowptr[NN];
__device__ int g_cursor[NN];
__device__ int g_bsum[NBLK];
__device__ int g_csrc[ET];

__device__ __forceinline__ float lrelu(float x) { return x > 0.f ? x : 0.2f * x; }

// f32x2 packed helpers (Blackwell FFMA2)
__device__ __forceinline__ u64 pack2(float x, float y) {
    u64 r; asm("mov.b64 %0,{%1,%2};" : "=l"(r) : "f"(x), "f"(y)); return r;
}
__device__ __forceinline__ void fma2(u64& d, u64 a, u64 b) {
    asm("fma.rn.f32x2 %0,%1,%2,%0;" : "+l"(d) : "l"(a), "l"(b));
}
__device__ __forceinline__ float2 unpack2(u64 v) {
    float x, y; asm("mov.b64 {%0,%1},%2;" : "=f"(x), "=f"(y) : "l"(v));
    return make_float2(x, y);
}

// ---------------- CSR build ----------------
// g_deg must be zero at entry: zero-init at load, re-zeroed by pool_kernel.
__global__ void hist_kernel(const int* __restrict__ ei) {
    int i = blockIdx.x * blockDim.x + threadIdx.x;
    if (i >= ET) return;
    int dst = (i < EE) ? ei[EE + i] : (i - EE);
    atomicAdd(&g_deg[dst], 1);
}

__global__ void scan1_kernel() {
    __shared__ int buf[1024];
    int t = threadIdx.x;
    int i = blockIdx.x * 1024 + t;
    int v = (i < NN) ? g_deg[i] : 0;
    buf[t] = v;
    __syncthreads();
    for (int off = 1; off < 1024; off <<= 1) {
        int add = (t >= off) ? buf[t - off] : 0;
        __syncthreads();
        buf[t] += add;
        __syncthreads();
    }
    if (i < NN) g_scan[i] = buf[t];
    if (t == 1023) g_bsum[blockIdx.x] = buf[1023];
}

// fused scan2+scan3: each block re-scans the 98 block sums locally
__global__ void scan3_kernel() {
    __shared__ int sb[128];
    __shared__ int ex[128];
    int t = threadIdx.x;
    int v0 = 0;
    if (t < 128) {
        v0 = (t < NBLK) ? g_bsum[t] : 0;
        sb[t] = v0;
    }
    __syncthreads();
    for (int off = 1; off < 128; off <<= 1) {
        int add = (t < 128 && t >= off) ? sb[t - off] : 0;
        __syncthreads();
        if (t < 128) sb[t] += add;
        __syncthreads();
    }
    if (t < 128) ex[t] = sb[t] - v0;  // exclusive
    __syncthreads();

    int i = blockIdx.x * blockDim.x + t;
    if (i >= NN) return;
    int rp = g_scan[i] - g_deg[i] + ex[i >> 10];
    g_rowptr[i] = rp;
    g_cursor[i] = rp;
}

__global__ void scatter_kernel(const int* __restrict__ ei) {
    int i = blockIdx.x * blockDim.x + threadIdx.x;
    if (i >= ET) return;
    int src, dst;
    if (i < EE) { src = ei[i]; dst = ei[EE + i]; }
    else        { src = i - EE; dst = i - EE; }
    int pos = atomicAdd(&g_cursor[dst], 1);
    g_csrc[pos] = src;
}

// ---------------- fused GEMM + attention logits (register-tiled, R7) -------
// Block: 256 threads, tile 64 nodes x 64 channels, K in chunks of 64.
// Thread (c4 = tid&15, n4 = tid>>4) computes nodes [4*n4,4*n4+4) x ch [4*c4,4*c4+4).
template <int FIN, bool FROM_A>
__global__ void __launch_bounds__(256)
gemm_attn_kernel(const float* __restrict__ xin_ext,
                 const float* __restrict__ W,
                 const float* __restrict__ a_src,
                 const float* __restrict__ a_dst,
                 const float* __restrict__ pbias) {
    constexpr int NCH = FIN / 64;          // K chunks
    __shared__ __align__(16) float Ws[64 * 64];   // W chunk [k][64]
    __shared__ __align__(16) float Xt[64 * 68];   // x chunk transposed [k][node], stride 68
    __shared__ float Aat[128];                    // [0:64) a_src, [64:128) a_dst
    __shared__ float Pb[FIN];

    int tid = threadIdx.x;
    int nbase = blockIdx.x * 64;
    int c4 = tid & 15;
    int n4 = tid >> 4;

    if (tid < 64)       Aat[tid] = a_src[tid];
    else if (tid < 128) Aat[tid] = a_dst[tid - 64];
    if (FROM_A) {
        for (int i = tid; i < FIN; i += 256) Pb[i] = pbias[i];
    }

    const float* xin = FROM_A ? (const float*)g_A : xin_ext;

    u64 acc[8];
#pragma unroll
    for (int j = 0; j < 8; j++) acc[j] = 0ull;

    for (int ch = 0; ch < NCH; ch++) {
        __syncthreads();
        for (int i = tid; i < 64 * 64; i += 256) Ws[i] = W[ch * 64 * 64 + i];
        for (int idx = tid; idx < 64 * 16; idx += 256) {
            int node = idx & 63;
            int k4 = idx >> 6;
            int gn = nbase + node;
            float4 v = make_float4(0.f, 0.f, 0.f, 0.f);
            if (gn < NN)
                v = reinterpret_cast<const float4*>(xin + (size_t)gn * FIN)[ch * 16 + k4];
            if (FROM_A) {
                v.x = fmaxf(v.x + Pb[ch * 64 + 4 * k4 + 0], 0.f);
                v.y = fmaxf(v.y + Pb[ch * 64 + 4 * k4 + 1], 0.f);
                v.z = fmaxf(v.z + Pb[ch * 64 + 4 * k4 + 2], 0.f);
                v.w = fmaxf(v.w + Pb[ch * 64 + 4 * k4 + 3], 0.f);
            }
            Xt[(4 * k4 + 0) * 68 + node] = v.x;
            Xt[(4 * k4 + 1) * 68 + node] = v.y;
            Xt[(4 * k4 + 2) * 68 + node] = v.z;
            Xt[(4 * k4 + 3) * 68 + node] = v.w;
        }
        __syncthreads();

#pragma unroll 4
        for (int k = 0; k < 64; k++) {
            double2 wd = *reinterpret_cast<const double2*>(&Ws[k * 64 + c4 * 4]);
            float4 xv = *reinterpret_cast<const float4*>(&Xt[k * 68 + n4 * 4]);
            u64 w0 = (u64)__double_as_longlong(wd.x);
            u64 w1 = (u64)__double_as_longlong(wd.y);
            u64 x0 = pack2(xv.x, xv.x);
            u64 x1 = pack2(xv.y, xv.y);
            u64 x2 = pack2(xv.z, xv.z);
            u64 x3 = pack2(xv.w, xv.w);
            fma2(acc[0], x0, w0); fma2(acc[1], x0, w1);
            fma2(acc[2], x1, w0); fma2(acc[3], x1, w1);
            fma2(acc[4], x2, w0); fma2(acc[5], x2, w1);
            fma2(acc[6], x3, w0); fma2(acc[7], x3, w1);
        }
    }

    // ---- epilogue ----
    int head = c4 >> 2;
    int cq = c4 & 3;
    float As0 = Aat[c4 * 4 + 0], As1 = Aat[c4 * 4 + 1];
    float As2 = Aat[c4 * 4 + 2], As3 = Aat[c4 * 4 + 3];
    float Ad0 = Aat[64 + c4 * 4 + 0], Ad1 = Aat[64 + c4 * 4 + 1];
    float Ad2 = Aat[64 + c4 * 4 + 2], Ad3 = Aat[64 + c4 * 4 + 3];

#pragma unroll
    for (int nn = 0; nn < 4; nn++) {
        float2 lo = unpack2(acc[nn * 2 + 0]);
        float2 hi = unpack2(acc[nn * 2 + 1]);
        int gn = nbase + n4 * 4 + nn;

        if (gn < NN) {
            __half2 h0 = __floats2half2_rn(lo.x, lo.y);
            __half2 h1 = __floats2half2_rn(hi.x, hi.y);
            uint2 pk;
            pk.x = *reinterpret_cast<unsigned*>(&h0);
            pk.y = *reinterpret_cast<unsigned*>(&h1);
            *reinterpret_cast<uint2*>(g_Hh + (size_t)gn * 64 + c4 * 4) = pk;
        }

        float ss = lo.x * As0 + lo.y * As1 + hi.x * As2 + hi.y * As3;
        float dd = lo.x * Ad0 + lo.y * Ad1 + hi.x * Ad2 + hi.y * Ad3;
        ss += __shfl_xor_sync(0xFFFFFFFFu, ss, 1);
        ss += __shfl_xor_sync(0xFFFFFFFFu, ss, 2);
        dd += __shfl_xor_sync(0xFFFFFFFFu, dd, 1);
        dd += __shfl_xor_sync(0xFFFFFFFFu, dd, 2);
        if (cq == 0 && gn < NN) {
            g_als[gn * 4 + head] = ss;
            g_ald[gn * 4 + head] = dd;
        }
    }
}

// ---------------- fused softmax + aggregation (gather, warp per dst node) ----
// (R7-verified version: full float4 butterfly for the exp sums — every lane
// needs ALL four head sums since lane->head mapping differs from lane->edge.)
__global__ void __launch_bounds__(256) gat_aggregate_kernel() {
    __shared__ int    s_s[WPB][32];
    __shared__ float4 s_w[WPB][32];

    int w = threadIdx.x >> 5;
    int lane = threadIdx.x & 31;
    int n = blockIdx.x * WPB + w;
    if (n >= NN) return;

    int beg = g_rowptr[n];
    int deg = g_deg[n];
    float4 ad = *reinterpret_cast<const float4*>(g_ald + n * 4);

    int head = lane >> 3;          // lane owns channels (2*lane, 2*lane+1)
    float accx = 0.f, accy = 0.f;
    float4 sw;

    const __half2* Hp = reinterpret_cast<const __half2*>(g_Hh);

    if (deg <= 32) {
        // ---- fast path: single gather of als, one chunk ----
        int s_reg = 0;
        float4 a = make_float4(-1e30f, -1e30f, -1e30f, -1e30f);
        bool act = lane < deg;
        if (act) {
            s_reg = g_csrc[beg + lane];
            a = *reinterpret_cast<const float4*>(g_als + s_reg * 4);
        }
        float4 mx = a;
#pragma unroll
        for (int off = 16; off; off >>= 1) {
            mx.x = fmaxf(mx.x, __shfl_xor_sync(0xFFFFFFFFu, mx.x, off));
            mx.y = fmaxf(mx.y, __shfl_xor_sync(0xFFFFFFFFu, mx.y, off));
            mx.z = fmaxf(mx.z, __shfl_xor_sync(0xFFFFFFFFu, mx.z, off));
            mx.w = fmaxf(mx.w, __shfl_xor_sync(0xFFFFFFFFu, mx.w, off));
        }
        float m0 = lrelu(mx.x + ad.x), m1 = lrelu(mx.y + ad.y);
        float m2 = lrelu(mx.z + ad.z), m3 = lrelu(mx.w + ad.w);

        float4 wv = make_float4(0.f, 0.f, 0.f, 0.f);
        if (act) {
            wv.x = __expf(lrelu(a.x + ad.x) - m0);
            wv.y = __expf(lrelu(a.y + ad.y) - m1);
            wv.z = __expf(lrelu(a.z + ad.z) - m2);
            wv.w = __expf(lrelu(a.w + ad.w) - m3);
            s_s[w][lane] = s_reg;
            s_w[w][lane] = wv;
        }
        sw = wv;
        __syncwarp();

        const float* wp = reinterpret_cast<const float*>(&s_w[w][0]);
#pragma unroll 8
        for (int j = 0; j < deg; j++) {
            int s0 = s_s[w][j];
            float w0 = wp[j * 4 + head];
            float2 f = __half22float2(Hp[(size_t)s0 * 32 + lane]);
            accx = fmaf(w0, f.x, accx);
            accy = fmaf(w0, f.y, accy);
        }
    } else {
        // ---- general path (rare): two-pass chunked ----
        float4 mx = make_float4(-1e30f, -1e30f, -1e30f, -1e30f);
        for (int i = lane; i < deg; i += 32) {
            int s = g_csrc[beg + i];
            float4 a = *reinterpret_cast<const float4*>(g_als + s * 4);
            mx.x = fmaxf(mx.x, a.x); mx.y = fmaxf(mx.y, a.y);
            mx.z = fmaxf(mx.z, a.z); mx.w = fmaxf(mx.w, a.w);
        }
#pragma unroll
        for (int off = 16; off; off >>= 1) {
            mx.x = fmaxf(mx.x, __shfl_xor_sync(0xFFFFFFFFu, mx.x, off));
            mx.y = fmaxf(mx.y, __shfl_xor_sync(0xFFFFFFFFu, mx.y, off));
            mx.z = fmaxf(mx.z, __shfl_xor_sync(0xFFFFFFFFu, mx.z, off));
            mx.w = fmaxf(mx.w, __shfl_xor_sync(0xFFFFFFFFu, mx.w, off));
        }
        float m0 = lrelu(mx.x + ad.x), m1 = lrelu(mx.y + ad.y);
        float m2 = lrelu(mx.z + ad.z), m3 = lrelu(mx.w + ad.w);

        sw = make_float4(0.f, 0.f, 0.f, 0.f);
        for (int base = 0; base < deg; base += 32) {
            int i = base + lane;
            if (i < deg) {
                int s = g_csrc[beg + i];
                float4 a = *reinterpret_cast<const float4*>(g_als + s * 4);
                float4 wv;
                wv.x = __expf(lrelu(a.x + ad.x) - m0);
                wv.y = __expf(lrelu(a.y + ad.y) - m1);
                wv.z = __expf(lrelu(a.z + ad.z) - m2);
                wv.w = __expf(lrelu(a.w + ad.w) - m3);
                sw.x += wv.x; sw.y += wv.y; sw.z += wv.z; sw.w += wv.w;
                s_s[w][lane] = s;
                s_w[w][lane] = wv;
            }
            __syncwarp();
            int cnt = min(32, deg - base);
            const float* wp = reinterpret_cast<const float*>(&s_w[w][0]);
#pragma unroll 8
            for (int j = 0; j < cnt; j++) {
                int s0 = s_s[w][j];
                float w0 = wp[j * 4 + head];
                float2 f = __half22float2(Hp[(size_t)s0 * 32 + lane]);
                accx = fmaf(w0, f.x, accx);
                accy = fmaf(w0, f.y, accy);
            }
            __syncwarp();
        }
    }

    // warp-reduce the exp sums (full float4 — correctness-critical)
#pragma unroll
    for (int off = 16; off; off >>= 1) {
        sw.x += __shfl_xor_sync(0xFFFFFFFFu, sw.x, off);
        sw.y += __shfl_xor_sync(0xFFFFFFFFu, sw.y, off);
        sw.z += __shfl_xor_sync(0xFFFFFFFFu, sw.z, off);
        sw.w += __shfl_xor_sync(0xFFFFFFFFu, sw.w, off);
    }
    float sh = (head == 0) ? sw.x : (head == 1) ? sw.y : (head == 2) ? sw.z : sw.w;
    float inv = 1.f / (sh + 1e-16f);
    *reinterpret_cast<float2*>(g_A + (size_t)n * 64 + 2 * lane) =
        make_float2(accx * inv, accy * inv);
}

// ---------------- output init + pooling + head ----------------
__global__ void init_out_kernel(float* out, const float* __restrict__ hb) {
    int g = blockIdx.x * blockDim.x + threadIdx.x;
    if (g < GG) out[g] = hb[0];
}

__global__ void pool_kernel(const float* __restrict__ b2,
                            const float* __restrict__ hw,
                            const int* __restrict__ batch,
                            float* out) {
    __shared__ float sb[64], sw[64];
    int tid = threadIdx.x;
    if (tid < 64) { sb[tid] = b2[tid]; sw[tid] = hw[tid]; }
    __syncthreads();

    long long t = (long long)blockIdx.x * blockDim.x + tid;
    int n = (int)(t >> 5);
    int lane = (int)(t & 31);
    if (n >= NN) return;

    const float* ar = g_A + (size_t)n * 64;
    float sm = fmaxf(ar[lane] + sb[lane], 0.f) * sw[lane]
             + fmaxf(ar[lane + 32] + sb[lane + 32], 0.f) * sw[lane + 32];
#pragma unroll
    for (int off = 16; off > 0; off >>= 1)
        sm += __shfl_down_sync(0xFFFFFFFFu, sm, off);
    if (lane == 0) {
        atomicAdd(&out[batch[n]], sm);
        g_deg[n] = 0;   // restore CSR-build invariant for the next replay
    }
}

// ---------------- launch ----------------
extern "C" void kernel_launch(void* const* d_in, const int* in_sizes, int n_in,
                              void* d_out, int out_size) {
    const float* x     = (const float*)d_in[0];
    const int*   ei    = (const int*)d_in[1];
    const int*   batch = (const int*)d_in[2];
    const float* W0  = (const float*)d_in[3];
    const float* as0 = (const float*)d_in[4];
    const float* ad0 = (const float*)d_in[5];
    const float* b0  = (const float*)d_in[6];
    const float* W1  = (const float*)d_in[7];
    const float* as1 = (const float*)d_in[8];
    const float* ad1 = (const float*)d_in[9];
    const float* b1  = (const float*)d_in[10];
    const float* W2  = (const float*)d_in[11];
    const float* as2 = (const float*)d_in[12];
    const float* ad2 = (const float*)d_in[13];
    const float* b2  = (const float*)d_in[14];
    const float* hw  = (const float*)d_in[15];
    const float* hb  = (const float*)d_in[16];
    float* out = (float*)d_out;

    const int EB = (ET + 255) / 256;
    const int NB = (NN + 255) / 256;
    const int GB = (NN + 63) / 64;    // 64 nodes per 256-thread block
    const int AB = (NN + WPB - 1) / WPB;
    const int PB = (int)(((long long)NN * 32 + 255) / 256);

    // CSR build; scatter at launch index 3 so ncu captures it this round
    hist_kernel<<<EB, 256>>>(ei);                                        // 0
    scan1_kernel<<<NBLK, 1024>>>();                                      // 1
    scan3_kernel<<<NB, 256>>>();                                         // 2
    scatter_kernel<<<EB, 256>>>(ei);                                     // 3
    gemm_attn_kernel<128, false><<<GB, 256>>>(x, W0, as0, ad0, nullptr); // 4

    // layer 0 aggregate
    gat_aggregate_kernel<<<AB, 256>>>();

    // layer 1 (input = g_A with bias b0 + relu)
    gemm_attn_kernel<64, true><<<GB, 256>>>(nullptr, W1, as1, ad1, b0);
    gat_aggregate_kernel<<<AB, 256>>>();

    // layer 2 (input = g_A with bias b1 + relu)
    gemm_attn_kernel<64, true><<<GB, 256>>>(nullptr, W2, as2, ad2, b1);
    gat_aggregate_kernel<<<AB, 256>>>();

    // pooling + head (bias b2 + relu fused; also re-zeros g_deg)
    init_out_kernel<<<(GG + 255) / 256, 256>>>(out, hb);
    pool_kernel<<<PB, 256>>>(b2, hw, batch, out);
}

// round 11
// speedup vs baseline: 1.2903x; 1.1542x over previous
#include <cuda_runtime.h>
#include <cuda_fp16.h>

#define NN 100000
#define EE 1600000
#define ET (EE + NN)
#define GG 2048
#define NBLK ((NN + 1023) / 1024)
#define WPB 8

typedef unsigned long long u64;

// ---------------- scratch (device globals; no allocation) ----------------
__device__ __align__(16) __half g_Hh[(size_t)NN * 64];  // fp16 transformed features
__device__ __align__(16) float  g_A[(size_t)NN * 64];   // aggregated output
__device__ __align__(16) float  g_als[NN * 4];
__device__ __align__(16) float  g_ald[NN * 4];
__device__ int g_deg[NN];       // zero-initialized at load; re-zeroed by pool_kernel
__device__ int g_scan[NN];
__device__ int g_rowptr[NN];
__device__ int g_bsum[NBLK];
__device__ int g_rank[ET];      // per-edge rank within its dst bucket
__device__ int g_csrc[ET];

__device__ __forceinline__ float lrelu(float x) { return x > 0.f ? x : 0.2f * x; }

// f32x2 packed helpers (Blackwell FFMA2)
__device__ __forceinline__ u64 pack2(float x, float y) {
    u64 r; asm("mov.b64 %0,{%1,%2};" : "=l"(r) : "f"(x), "f"(y)); return r;
}
__device__ __forceinline__ void fma2(u64& d, u64 a, u64 b) {
    asm("fma.rn.f32x2 %0,%1,%2,%0;" : "+l"(d) : "l"(a), "l"(b));
}
__device__ __forceinline__ float2 unpack2(u64 v) {
    float x, y; asm("mov.b64 {%0,%1},%2;" : "=f"(x), "=f"(y) : "l"(v));
    return make_float2(x, y);
}

// ---------------- CSR build ----------------
// g_deg must be zero at entry: zero-init at load, re-zeroed by pool_kernel.
// hist also records each edge's rank within its dst bucket, so scatter
// needs NO atomics.
__global__ void hist_kernel(const int* __restrict__ ei) {
    int i = blockIdx.x * blockDim.x + threadIdx.x;
    if (i >= ET) return;
    int dst = (i < EE) ? ei[EE + i] : (i - EE);
    g_rank[i] = atomicAdd(&g_deg[dst], 1);
}

__global__ void scan1_kernel() {
    __shared__ int buf[1024];
    int t = threadIdx.x;
    int i = blockIdx.x * 1024 + t;
    int v = (i < NN) ? g_deg[i] : 0;
    buf[t] = v;
    __syncthreads();
    for (int off = 1; off < 1024; off <<= 1) {
        int add = (t >= off) ? buf[t - off] : 0;
        __syncthreads();
        buf[t] += add;
        __syncthreads();
    }
    if (i < NN) g_scan[i] = buf[t];
    if (t == 1023) g_bsum[blockIdx.x] = buf[1023];
}

// fused scan2+scan3: each block re-scans the 98 block sums locally
__global__ void scan3_kernel() {
    __shared__ int sb[128];
    __shared__ int ex[128];
    int t = threadIdx.x;
    int v0 = 0;
    if (t < 128) {
        v0 = (t < NBLK) ? g_bsum[t] : 0;
        sb[t] = v0;
    }
    __syncthreads();
    for (int off = 1; off < 128; off <<= 1) {
        int add = (t < 128 && t >= off) ? sb[t - off] : 0;
        __syncthreads();
        if (t < 128) sb[t] += add;
        __syncthreads();
    }
    if (t < 128) ex[t] = sb[t] - v0;  // exclusive
    __syncthreads();

    int i = blockIdx.x * blockDim.x + t;
    if (i >= NN) return;
    g_rowptr[i] = g_scan[i] - g_deg[i] + ex[i >> 10];  // exclusive prefix
}

// atomic-free scatter using precomputed ranks
__global__ void scatter_kernel(const int* __restrict__ ei) {
    int i = blockIdx.x * blockDim.x + threadIdx.x;
    if (i >= ET) return;
    int src, dst;
    if (i < EE) { src = ei[i]; dst = ei[EE + i]; }
    else        { src = i - EE; dst = i - EE; }
    g_csrc[g_rowptr[dst] + g_rank[i]] = src;
}

// ---------------- fused GEMM + attention logits (register-tiled, R7) -------
// Block: 256 threads, tile 64 nodes x 64 channels, K in chunks of 64.
// Thread (c4 = tid&15, n4 = tid>>4) computes nodes [4*n4,4*n4+4) x ch [4*c4,4*c4+4).
template <int FIN, bool FROM_A>
__global__ void __launch_bounds__(256)
gemm_attn_kernel(const float* __restrict__ xin_ext,
                 const float* __restrict__ W,
                 const float* __restrict__ a_src,
                 const float* __restrict__ a_dst,
                 const float* __restrict__ pbias) {
    constexpr int NCH = FIN / 64;          // K chunks
    __shared__ __align__(16) float Ws[64 * 64];   // W chunk [k][64]
    __shared__ __align__(16) float Xt[64 * 68];   // x chunk transposed [k][node], stride 68
    __shared__ float Aat[128];                    // [0:64) a_src, [64:128) a_dst
    __shared__ float Pb[FIN];

    int tid = threadIdx.x;
    int nbase = blockIdx.x * 64;
    int c4 = tid & 15;
    int n4 = tid >> 4;

    if (tid < 64)       Aat[tid] = a_src[tid];
    else if (tid < 128) Aat[tid] = a_dst[tid - 64];
    if (FROM_A) {
        for (int i = tid; i < FIN; i += 256) Pb[i] = pbias[i];
    }

    const float* xin = FROM_A ? (const float*)g_A : xin_ext;

    u64 acc[8];
#pragma unroll
    for (int j = 0; j < 8; j++) acc[j] = 0ull;

    for (int ch = 0; ch < NCH; ch++) {
        __syncthreads();
        for (int i = tid; i < 64 * 64; i += 256) Ws[i] = W[ch * 64 * 64 + i];
        for (int idx = tid; idx < 64 * 16; idx += 256) {
            int node = idx & 63;
            int k4 = idx >> 6;
            int gn = nbase + node;
            float4 v = make_float4(0.f, 0.f, 0.f, 0.f);
            if (gn < NN)
                v = reinterpret_cast<const float4*>(xin + (size_t)gn * FIN)[ch * 16 + k4];
            if (FROM_A) {
                v.x = fmaxf(v.x + Pb[ch * 64 + 4 * k4 + 0], 0.f);
                v.y = fmaxf(v.y + Pb[ch * 64 + 4 * k4 + 1], 0.f);
                v.z = fmaxf(v.z + Pb[ch * 64 + 4 * k4 + 2], 0.f);
                v.w = fmaxf(v.w + Pb[ch * 64 + 4 * k4 + 3], 0.f);
            }
            Xt[(4 * k4 + 0) * 68 + node] = v.x;
            Xt[(4 * k4 + 1) * 68 + node] = v.y;
            Xt[(4 * k4 + 2) * 68 + node] = v.z;
            Xt[(4 * k4 + 3) * 68 + node] = v.w;
        }
        __syncthreads();

#pragma unroll 4
        for (int k = 0; k < 64; k++) {
            double2 wd = *reinterpret_cast<const double2*>(&Ws[k * 64 + c4 * 4]);
            float4 xv = *reinterpret_cast<const float4*>(&Xt[k * 68 + n4 * 4]);
            u64 w0 = (u64)__double_as_longlong(wd.x);
            u64 w1 = (u64)__double_as_longlong(wd.y);
            u64 x0 = pack2(xv.x, xv.x);
            u64 x1 = pack2(xv.y, xv.y);
            u64 x2 = pack2(xv.z, xv.z);
            u64 x3 = pack2(xv.w, xv.w);
            fma2(acc[0], x0, w0); fma2(acc[1], x0, w1);
            fma2(acc[2], x1, w0); fma2(acc[3], x1, w1);
            fma2(acc[4], x2, w0); fma2(acc[5], x2, w1);
            fma2(acc[6], x3, w0); fma2(acc[7], x3, w1);
        }
    }

    // ---- epilogue ----
    int head = c4 >> 2;
    int cq = c4 & 3;
    float As0 = Aat[c4 * 4 + 0], As1 = Aat[c4 * 4 + 1];
    float As2 = Aat[c4 * 4 + 2], As3 = Aat[c4 * 4 + 3];
    float Ad0 = Aat[64 + c4 * 4 + 0], Ad1 = Aat[64 + c4 * 4 + 1];
    float Ad2 = Aat[64 + c4 * 4 + 2], Ad3 = Aat[64 + c4 * 4 + 3];

#pragma unroll
    for (int nn = 0; nn < 4; nn++) {
        float2 lo = unpack2(acc[nn * 2 + 0]);
        float2 hi = unpack2(acc[nn * 2 + 1]);
        int gn = nbase + n4 * 4 + nn;

        if (gn < NN) {
            __half2 h0 = __floats2half2_rn(lo.x, lo.y);
            __half2 h1 = __floats2half2_rn(hi.x, hi.y);
            uint2 pk;
            pk.x = *reinterpret_cast<unsigned*>(&h0);
            pk.y = *reinterpret_cast<unsigned*>(&h1);
            *reinterpret_cast<uint2*>(g_Hh + (size_t)gn * 64 + c4 * 4) = pk;
        }

        float ss = lo.x * As0 + lo.y * As1 + hi.x * As2 + hi.y * As3;
        float dd = lo.x * Ad0 + lo.y * Ad1 + hi.x * Ad2 + hi.y * Ad3;
        ss += __shfl_xor_sync(0xFFFFFFFFu, ss, 1);
        ss += __shfl_xor_sync(0xFFFFFFFFu, ss, 2);
        dd += __shfl_xor_sync(0xFFFFFFFFu, dd, 1);
        dd += __shfl_xor_sync(0xFFFFFFFFu, dd, 2);
        if (cq == 0 && gn < NN) {
            g_als[gn * 4 + head] = ss;
            g_ald[gn * 4 + head] = dd;
        }
    }
}

// ---------------- fused softmax + aggregation (max-free, gather) -----------
// alpha = exp(lg) / sum(exp(lg)); logits are O(1) so exp cannot overflow.
// Each lane accumulates its own head's exp-sum inside the j-loop (the smem
// weight it reads, wp[j*4+head], IS its head's component for edge j).
__global__ void __launch_bounds__(256) gat_aggregate_kernel() {
    __shared__ int    s_s[WPB][32];
    __shared__ float4 s_w[WPB][32];

    int w = threadIdx.x >> 5;
    int lane = threadIdx.x & 31;
    int n = blockIdx.x * WPB + w;
    if (n >= NN) return;

    int beg = g_rowptr[n];
    int deg = g_deg[n];
    float4 ad = *reinterpret_cast<const float4*>(g_ald + n * 4);

    int head = lane >> 3;          // lane owns channels (2*lane, 2*lane+1)
    float accx = 0.f, accy = 0.f;
    float swh = 0.f;               // this lane's head exp-sum

    const __half2* Hp = reinterpret_cast<const __half2*>(g_Hh);

    if (deg <= 32) {
        // ---- fast path: one gather, one chunk, no max phase ----
        if (lane < deg) {
            int s_reg = g_csrc[beg + lane];
            float4 a = *reinterpret_cast<const float4*>(g_als + s_reg * 4);
            float4 wv;
            wv.x = __expf(lrelu(a.x + ad.x));
            wv.y = __expf(lrelu(a.y + ad.y));
            wv.z = __expf(lrelu(a.z + ad.z));
            wv.w = __expf(lrelu(a.w + ad.w));
            s_s[w][lane] = s_reg;
            s_w[w][lane] = wv;
        }
        __syncwarp();

        const float* wp = reinterpret_cast<const float*>(&s_w[w][0]);
#pragma unroll 8
        for (int j = 0; j < deg; j++) {
            int s0 = s_s[w][j];
            float w0 = wp[j * 4 + head];
            swh += w0;
            float2 f = __half22float2(Hp[(size_t)s0 * 32 + lane]);
            accx = fmaf(w0, f.x, accx);
            accy = fmaf(w0, f.y, accy);
        }
    } else {
        // ---- general path (rare): chunked, no max phase ----
        for (int base = 0; base < deg; base += 32) {
            int i = base + lane;
            if (i < deg) {
                int s = g_csrc[beg + i];
                float4 a = *reinterpret_cast<const float4*>(g_als + s * 4);
                float4 wv;
                wv.x = __expf(lrelu(a.x + ad.x));
                wv.y = __expf(lrelu(a.y + ad.y));
                wv.z = __expf(lrelu(a.z + ad.z));
                wv.w = __expf(lrelu(a.w + ad.w));
                s_s[w][lane] = s;
                s_w[w][lane] = wv;
            }
            __syncwarp();
            int cnt = min(32, deg - base);
            const float* wp = reinterpret_cast<const float*>(&s_w[w][0]);
#pragma unroll 8
            for (int j = 0; j < cnt; j++) {
                int s0 = s_s[w][j];
                float w0 = wp[j * 4 + head];
                swh += w0;
                float2 f = __half22float2(Hp[(size_t)s0 * 32 + lane]);
                accx = fmaf(w0, f.x, accx);
                accy = fmaf(w0, f.y, accy);
            }
            __syncwarp();
        }
    }

    float inv = 1.f / (swh + 1e-16f);
    *reinterpret_cast<float2*>(g_A + (size_t)n * 64 + 2 * lane) =
        make_float2(accx * inv, accy * inv);
}

// ---------------- output init + pooling + head ----------------
__global__ void init_out_kernel(float* out, const float* __restrict__ hb) {
    int g = blockIdx.x * blockDim.x + threadIdx.x;
    if (g < GG) out[g] = hb[0];
}

__global__ void pool_kernel(const float* __restrict__ b2,
                            const float* __restrict__ hw,
                            const int* __restrict__ batch,
                            float* out) {
    __shared__ float sb[64], sw[64];
    int tid = threadIdx.x;
    if (tid < 64) { sb[tid] = b2[tid]; sw[tid] = hw[tid]; }
    __syncthreads();

    long long t = (long long)blockIdx.x * blockDim.x + tid;
    int n = (int)(t >> 5);
    int lane = (int)(t & 31);
    if (n >= NN) return;

    const float* ar = g_A + (size_t)n * 64;
    float sm = fmaxf(ar[lane] + sb[lane], 0.f) * sw[lane]
             + fmaxf(ar[lane + 32] + sb[lane + 32], 0.f) * sw[lane + 32];
#pragma unroll
    for (int off = 16; off > 0; off >>= 1)
        sm += __shfl_down_sync(0xFFFFFFFFu, sm, off);
    if (lane == 0) {
        atomicAdd(&out[batch[n]], sm);
        g_deg[n] = 0;   // restore CSR-build invariant for the next replay
    }
}

// ---------------- launch ----------------
extern "C" void kernel_launch(void* const* d_in, const int* in_sizes, int n_in,
                              void* d_out, int out_size) {
    const float* x     = (const float*)d_in[0];
    const int*   ei    = (const int*)d_in[1];
    const int*   batch = (const int*)d_in[2];
    const float* W0  = (const float*)d_in[3];
    const float* as0 = (const float*)d_in[4];
    const float* ad0 = (const float*)d_in[5];
    const float* b0  = (const float*)d_in[6];
    const float* W1  = (const float*)d_in[7];
    const float* as1 = (const float*)d_in[8];
    const float* ad1 = (const float*)d_in[9];
    const float* b1  = (const float*)d_in[10];
    const float* W2  = (const float*)d_in[11];
    const float* as2 = (const float*)d_in[12];
    const float* ad2 = (const float*)d_in[13];
    const float* b2  = (const float*)d_in[14];
    const float* hw  = (const float*)d_in[15];
    const float* hb  = (const float*)d_in[16];
    float* out = (float*)d_out;

    const int EB = (ET + 255) / 256;
    const int NB = (NN + 255) / 256;
    const int GB = (NN + 63) / 64;    // 64 nodes per 256-thread block
    const int AB = (NN + WPB - 1) / WPB;
    const int PB = (int)(((long long)NN * 32 + 255) / 256);

    // CSR build; rank-based scatter at capture index 3 for verification
    hist_kernel<<<EB, 256>>>(ei);                                        // 0
    scan1_kernel<<<NBLK, 1024>>>();                                      // 1
    scan3_kernel<<<NB, 256>>>();                                         // 2
    scatter_kernel<<<EB, 256>>>(ei);                                     // 3
    gemm_attn_kernel<128, false><<<GB, 256>>>(x, W0, as0, ad0, nullptr); // 4

    // layer 0 aggregate
    gat_aggregate_kernel<<<AB, 256>>>();

    // layer 1 (input = g_A with bias b0 + relu)
    gemm_attn_kernel<64, true><<<GB, 256>>>(nullptr, W1, as1, ad1, b0);
    gat_aggregate_kernel<<<AB, 256>>>();

    // layer 2 (input = g_A with bias b1 + relu)
    gemm_attn_kernel<64, true><<<GB, 256>>>(nullptr, W2, as2, ad2, b1);
    gat_aggregate_kernel<<<AB, 256>>>();

    // pooling + head (bias b2 + relu fused; also re-zeros g_deg)
    init_out_kernel<<<(GG + 255) / 256, 256>>>(out, hb);
    pool_kernel<<<PB, 256>>>(b2, hw, batch, out);
}